// round 14
// baseline (speedup 1.0000x reference)
#include <cuda_runtime.h>
#include <cuda_fp16.h>
#include <cstdint>

#define NN   8192
#define INF_ 128
#define HIDF 256
#define OUTF 64

// ---------------- scratch (device globals; no allocations allowed) ----------
// NOTE: only ever referenced from device code (host shadow-address bug, R2/R3).
static __device__ __half g_adjh[(size_t)NN * NN];     // adj in fp16 (128 MB)
static __device__ float  g_d[NN];                     // 1/sqrt(deg+eps)
static __device__ __half g_xsT[(size_t)INF_ * NN];    // (d*x)^T  [128][8192]
static __device__ __half g_t1h[(size_t)NN * INF_];    // d⊙(adj@x̃) fp16
static __device__ float  g_t1p[4][(size_t)NN * INF_]; // GEMM1 split-K partials
static __device__ __half g_w1h[(size_t)HIDF * INF_];  // W1 fp16 [256][128]
static __device__ __half g_w2h[(size_t)OUTF * HIDF];  // W2 fp16 [64][256]
static __device__ __half g_h  [(size_t)NN * HIDF];    // relu(t1@W1T+b1) fp16
static __device__ __half g_p  [(size_t)NN * OUTF];    // d*2^14*(h@W2T) fp16
static __device__ __half g_pT [(size_t)OUTF * NN];    // transposed [64][8192]
static __device__ float  g_part[8][(size_t)NN * OUTF]; // GEMM2 split-K partials

// ---------------- helpers ---------------------------------------------------
__device__ __forceinline__ uint32_t smem_u32(const void* p) {
    uint32_t a;
    asm("{ .reg .u64 t; cvta.to.shared.u64 t, %1; cvt.u32.u64 %0, t; }"
        : "=r"(a) : "l"(p));
    return a;
}
__device__ __forceinline__ void cp_async16s(uint32_t s, const void* g) {
    asm volatile("cp.async.cg.shared.global [%0], [%1], 16;\n" :: "r"(s), "l"(g));
}
#define CP_COMMIT() asm volatile("cp.async.commit_group;\n")
#define CP_WAIT(n)  asm volatile("cp.async.wait_group %0;\n" :: "n"(n))

__device__ __forceinline__ void mma16816(float* c, const uint32_t* a, const uint32_t* b) {
    asm volatile(
        "mma.sync.aligned.m16n8k16.row.col.f32.f16.f16.f32 "
        "{%0,%1,%2,%3}, {%4,%5,%6,%7}, {%8,%9}, {%0,%1,%2,%3};\n"
        : "+f"(c[0]), "+f"(c[1]), "+f"(c[2]), "+f"(c[3])
        : "r"(a[0]), "r"(a[1]), "r"(a[2]), "r"(a[3]), "r"(b[0]), "r"(b[1]));
}
__device__ __forceinline__ void ldsm_x4(uint32_t* r, uint32_t addr) {
    asm volatile("ldmatrix.sync.aligned.m8n8.x4.shared.b16 {%0,%1,%2,%3}, [%4];"
        : "=r"(r[0]), "=r"(r[1]), "=r"(r[2]), "=r"(r[3]) : "r"(addr));
}

// ---------------- kernel 1: row-sum + fp32->fp16 convert, one pass ----------
__global__ void __launch_bounds__(256) k_deg_convert(const float* __restrict__ adj) {
    int row = blockIdx.x;
    const float4* src = reinterpret_cast<const float4*>(adj + (size_t)row * NN);
    uint2* dst = reinterpret_cast<uint2*>(g_adjh + (size_t)row * NN);
    float s = 0.f;
    for (int i = threadIdx.x; i < NN / 4; i += 256) {
        float4 v = src[i];
        s += (v.x + v.y) + (v.z + v.w);
        __half2 h0 = __floats2half2_rn(v.x, v.y);
        __half2 h1 = __floats2half2_rn(v.z, v.w);
        uint2 u;
        u.x = *reinterpret_cast<uint32_t*>(&h0);
        u.y = *reinterpret_cast<uint32_t*>(&h1);
        dst[i] = u;
    }
    __shared__ float red[8];
    for (int o = 16; o; o >>= 1) s += __shfl_xor_sync(0xffffffffu, s, o);
    if ((threadIdx.x & 31) == 0) red[threadIdx.x >> 5] = s;
    __syncthreads();
    if (threadIdx.x < 8) {
        float v = red[threadIdx.x];
        for (int o = 4; o; o >>= 1) v += __shfl_xor_sync(0xffu, v, o);
        if (threadIdx.x == 0) g_d[row] = rsqrtf(v + 1e-8f);
    }
}

// ---------------- kernel 2: x̃ᵀ[j][k] = fp16(d_k * x[k][j]) ------------------
__global__ void k_scale_x_T(const float* __restrict__ x) {
    __shared__ float tile[32][33];
    int k0 = blockIdx.x * 32, j0 = blockIdx.y * 32;
    int tx = threadIdx.x, ty = threadIdx.y;   // 32 x 8
    #pragma unroll
    for (int i = 0; i < 32; i += 8) {
        int k = k0 + ty + i;
        tile[ty + i][tx] = x[(size_t)k * INF_ + j0 + tx] * g_d[k];
    }
    __syncthreads();
    #pragma unroll
    for (int i = 0; i < 32; i += 8)
        g_xsT[(size_t)(j0 + ty + i) * NN + k0 + tx] = __float2half(tile[tx][ty + i]);
}

// ---------------- weights -> fp16 -------------------------------------------
__global__ void __launch_bounds__(256) k_convert_w(const float* __restrict__ W1,
                                                   const float* __restrict__ W2) {
    int i = blockIdx.x * 256 + threadIdx.x;
    if (i < HIDF * INF_) g_w1h[i] = __float2half(W1[i]);
    if (i < OUTF * HIDF) g_w2h[i] = __float2half(W2[i]);
}

// ---------------- unified HMMA GEMM ------------------------------------------
// CTA tile 128x64, 128 threads = 4 warps (wm2 x wn2), warp tile 64x32.
// BK=64, S=2, pitch 72, 3 CTAs/SM (55.3 KB smem, <=170 regs).
// KK = K elements per CTA.
// MODE 0 (t1):   A=adjh, B=xsT. grid.y(8): bit0=N-tile, bits1-2=K-quarter.
//                raw fp32 -> g_t1p[y>>1].
// MODE 1 (mlp1): A=g_t1h(128), B=g_w1h(128), grid.y = N-tile(4), epi relu+b.
// MODE 2 (mlp2): A=g_h(256),   B=g_w2h(256), grid.y=1, epi d*2^14 -> g_p.
// MODE 3 (out):  A=adjh, B=pT. grid.y = K-eighth(8), raw fp32 -> g_part[y].
template<int LDA, int LDB, int KK, int MODE>
__global__ void __launch_bounds__(128, 3) k_gemm(float* __restrict__ C_arg,
                                                 const float* __restrict__ bias) {
    constexpr int S = 2;
    constexpr int BK = 64;                         // halves of K per stage
    constexpr int KT = KK / BK;
    constexpr int PITCH = BK + 8;                  // 72 halves per row
    constexpr int AH = 128 * PITCH;                // halves per A stage
    constexpr int BH = 64 * PITCH;                 // halves per B stage
    constexpr bool SPLITK = (MODE == 0 || MODE == 3);
    extern __shared__ __half smem_dyn[];
    __half* sAp = smem_dyn;                        // S * AH
    __half* sBp = smem_dyn + S * AH;               // S * BH

    // in-kernel symbol selection (host-shadow rule)
    const __half* A  = SPLITK ? g_adjh : (MODE == 1 ? g_t1h : g_h);
    const __half* BT = (MODE == 0) ? g_xsT
                     : (MODE == 1) ? g_w1h
                     : (MODE == 2) ? g_w2h : g_pT;

    int tid = threadIdx.x;
    int m0 = blockIdx.x * 128;
    int n0, koff;
    if constexpr (MODE == 0) { n0 = (blockIdx.y & 1) * 64; koff = (blockIdx.y >> 1) * KK; }
    else if constexpr (MODE == 3) { n0 = 0; koff = blockIdx.y * KK; }
    else { n0 = blockIdx.y * 64; koff = 0; }
    const __half* gA = A + (size_t)m0 * LDA + koff;
    const __half* gB = BT + (size_t)n0 * LDB + koff;

    const uint32_t uA = smem_u32(sAp);
    const uint32_t uB = smem_u32(sBp);

    auto load_stage = [&](int st, int kt) {
        const __half* a = gA + kt * BK;
        #pragma unroll
        for (int i = 0; i < 8; i++) {              // A: 128 rows x 8 chunks
            int c = tid + i * 128;
            int r = c >> 3, off = (c & 7) << 3;
            cp_async16s(uA + (uint32_t)((st * 128 + r) * PITCH + off) * 2,
                        a + (size_t)r * LDA + off);
        }
        const __half* b = gB + kt * BK;
        #pragma unroll
        for (int i = 0; i < 4; i++) {              // B: 64 rows x 8 chunks
            int c = tid + i * 128;
            int r = c >> 3, off = (c & 7) << 3;
            cp_async16s(uB + (uint32_t)((st * 64 + r) * PITCH + off) * 2,
                        b + (size_t)r * LDB + off);
        }
    };

    load_stage(0, 0);
    CP_COMMIT();

    int lane = tid & 31, warp = tid >> 5;          // 4 warps
    int wm = warp >> 1, wn = warp & 1;
    int g = lane >> 2, tg = lane & 3;

    // ldmatrix lane roles
    int a_row = (lane & 15);                       // + wm*64 + mt*16
    int a_kof = (lane >> 4) << 3;                  // halves within k16 group
    int b_row = (lane >> 4) * 8 + (lane & 7);      // + wn*32 + j*16
    int b_kof = ((lane >> 3) & 1) << 3;            // halves within k16 group

    float acc[4][4][4];
    #pragma unroll
    for (int mt = 0; mt < 4; mt++)
        #pragma unroll
        for (int nt = 0; nt < 4; nt++)
            #pragma unroll
            for (int i = 0; i < 4; i++) acc[mt][nt][i] = 0.f;

    uint32_t af[2][4][4], bf[2][4][2];
    auto ldfrags = [&](int fb, uint32_t bufA, uint32_t bufB, int ks) {
        #pragma unroll
        for (int mt = 0; mt < 4; mt++) {
            uint32_t addr = bufA
                + (uint32_t)((wm * 64 + mt * 16 + a_row) * PITCH
                             + ks * 16 + a_kof) * 2;
            ldsm_x4(af[fb][mt], addr);
        }
        #pragma unroll
        for (int j = 0; j < 2; j++) {
            uint32_t r4[4];
            uint32_t addr = bufB
                + (uint32_t)((wn * 32 + j * 16 + b_row) * PITCH
                             + ks * 16 + b_kof) * 2;
            ldsm_x4(r4, addr);
            bf[fb][2 * j][0] = r4[0]; bf[fb][2 * j][1] = r4[1];
            bf[fb][2 * j + 1][0] = r4[2]; bf[fb][2 * j + 1][1] = r4[3];
        }
    };

    for (int kt = 0; kt < KT; kt++) {
        CP_WAIT(0);
        __syncthreads();
        int buf = kt & 1;
        uint32_t bufA = uA + (uint32_t)(buf * AH) * 2;
        uint32_t bufB = uB + (uint32_t)(buf * BH) * 2;
        ldfrags(0, bufA, bufB, 0);                 // head frags
        if (kt + 1 < KT) load_stage((kt + 1) & 1, kt + 1);  // async next stage
        CP_COMMIT();
        #pragma unroll
        for (int ks = 0; ks < 4; ks++) {           // 4 k16 steps per stage
            int fb = ks & 1;
            if (ks < 3) ldfrags(fb ^ 1, bufA, bufB, ks + 1);
            #pragma unroll
            for (int mt = 0; mt < 4; mt++)
                #pragma unroll
                for (int nt = 0; nt < 4; nt++)
                    mma16816(acc[mt][nt], af[fb][mt], bf[fb][nt]);
        }
    }

    // ------ epilogue ------
    float* part = (MODE == 0) ? g_t1p[blockIdx.y >> 1]
                : (MODE == 3) ? g_part[blockIdx.y] : nullptr;
    constexpr int LDC = (MODE == 0) ? INF_ : OUTF;
    #pragma unroll
    for (int mt = 0; mt < 4; mt++) {
        int r0 = m0 + wm * 64 + mt * 16 + g;
        int r1 = r0 + 8;
        #pragma unroll
        for (int nt = 0; nt < 4; nt++) {
            int c = n0 + wn * 32 + nt * 8 + 2 * tg;
            float v00 = acc[mt][nt][0], v01 = acc[mt][nt][1];
            float v10 = acc[mt][nt][2], v11 = acc[mt][nt][3];
            if constexpr (SPLITK) {                // raw partials, combined later
                *(float2*)(part + (size_t)r0 * LDC + c) = make_float2(v00, v01);
                *(float2*)(part + (size_t)r1 * LDC + c) = make_float2(v10, v11);
            } else if constexpr (MODE == 1) {
                float b0 = bias[c], b1v = bias[c + 1];
                *(__half2*)(g_h + (size_t)r0 * HIDF + c) =
                    __floats2half2_rn(fmaxf(v00 + b0, 0.f), fmaxf(v01 + b1v, 0.f));
                *(__half2*)(g_h + (size_t)r1 * HIDF + c) =
                    __floats2half2_rn(fmaxf(v10 + b0, 0.f), fmaxf(v11 + b1v, 0.f));
            } else {                               // MODE 2
                float d0 = g_d[r0] * 16384.f, d1 = g_d[r1] * 16384.f;
                *(__half2*)(g_p + (size_t)r0 * OUTF + c) =
                    __floats2half2_rn(v00 * d0, v01 * d0);
                *(__half2*)(g_p + (size_t)r1 * OUTF + c) =
                    __floats2half2_rn(v10 * d1, v11 * d1);
            }
        }
    }
}

// ---------------- combine GEMM1 split-K: t1h = fp16(d * Σp) -----------------
__global__ void __launch_bounds__(256) k_combine_t1() {
    int idx = blockIdx.x * 256 + threadIdx.x;      // one float4-quad per thread
    int r = (idx * 4) / INF_;
    float4 a = *reinterpret_cast<const float4*>(&g_t1p[0][(size_t)idx * 4]);
    float4 b = *reinterpret_cast<const float4*>(&g_t1p[1][(size_t)idx * 4]);
    float4 e = *reinterpret_cast<const float4*>(&g_t1p[2][(size_t)idx * 4]);
    float4 f = *reinterpret_cast<const float4*>(&g_t1p[3][(size_t)idx * 4]);
    float dsc = g_d[r];
    float sx = (a.x + b.x) + (e.x + f.x);
    float sy = (a.y + b.y) + (e.y + f.y);
    float sz = (a.z + b.z) + (e.z + f.z);
    float sw = (a.w + b.w) + (e.w + f.w);
    __half2 h0 = __floats2half2_rn(sx * dsc, sy * dsc);
    __half2 h1 = __floats2half2_rn(sz * dsc, sw * dsc);
    uint2 u;
    u.x = *reinterpret_cast<uint32_t*>(&h0);
    u.y = *reinterpret_cast<uint32_t*>(&h1);
    *reinterpret_cast<uint2*>(g_t1h + (size_t)idx * 4) = u;
}

// ---------------- combine GEMM2 split-K: out = (Σp)*d/2^14 + b2 -------------
__global__ void __launch_bounds__(256) k_combine(float* __restrict__ out,
                                                 const float* __restrict__ b2) {
    int idx = blockIdx.x * 256 + threadIdx.x;      // one float4 per thread
    int r = (idx * 4) / OUTF, c = (idx * 4) % OUTF;
    float sx = 0.f, sy = 0.f, sz = 0.f, sw = 0.f;
    #pragma unroll
    for (int k = 0; k < 8; k++) {
        float4 v = *reinterpret_cast<const float4*>(&g_part[k][(size_t)idx * 4]);
        sx += v.x; sy += v.y; sz += v.z; sw += v.w;
    }
    float dsc = g_d[r] * (1.f / 16384.f);
    float4 o;
    o.x = sx * dsc + b2[c];
    o.y = sy * dsc + b2[c + 1];
    o.z = sz * dsc + b2[c + 2];
    o.w = sw * dsc + b2[c + 3];
    *reinterpret_cast<float4*>(out + (size_t)idx * 4) = o;
}

// ---------------- transpose g_p [8192,64] -> g_pT [64][8192] ----------------
__global__ void k_transpose_p() {
    __shared__ __half tile[32][33];
    int k0 = blockIdx.x * 32, c0 = blockIdx.y * 32;
    int tx = threadIdx.x, ty = threadIdx.y;   // 32 x 8
    #pragma unroll
    for (int i = 0; i < 32; i += 8)
        tile[ty + i][tx] = g_p[(size_t)(k0 + ty + i) * OUTF + c0 + tx];
    __syncthreads();
    #pragma unroll
    for (int i = 0; i < 32; i += 8)
        g_pT[(size_t)(c0 + ty + i) * NN + k0 + tx] = tile[tx][ty + i];
}

// ---------------- launch -----------------------------------------------------
extern "C" void kernel_launch(void* const* d_in, const int* in_sizes, int n_in,
                              void* d_out, int out_size) {
    const float* x   = (const float*)d_in[0];
    const float* adj = (const float*)d_in[1];
    const float* W1  = (const float*)d_in[2];
    const float* b1  = (const float*)d_in[3];
    const float* W2  = (const float*)d_in[4];
    const float* b2  = (const float*)d_in[5];
    float* out = (float*)d_out;

    // dynamic smem: S=2, 2*(128+64)*72 halves * 2B = 55296 (3 CTAs/SM: 165.9KB)
    constexpr int SMEM = 2 * (128 + 64) * 72 * 2;
    cudaFuncSetAttribute(k_gemm<NN, NN, NN / 4, 0>,
                         cudaFuncAttributeMaxDynamicSharedMemorySize, SMEM);
    cudaFuncSetAttribute(k_gemm<INF_, INF_, INF_, 1>,
                         cudaFuncAttributeMaxDynamicSharedMemorySize, SMEM);
    cudaFuncSetAttribute(k_gemm<HIDF, HIDF, HIDF, 2>,
                         cudaFuncAttributeMaxDynamicSharedMemorySize, SMEM);
    cudaFuncSetAttribute(k_gemm<NN, NN, NN / 8, 3>,
                         cudaFuncAttributeMaxDynamicSharedMemorySize, SMEM);

    // 1) degrees + adj->fp16 (one pass over 256 MB)
    k_deg_convert<<<NN, 256>>>(adj);
    // 2) x̃ᵀ = (d ⊙ x)ᵀ fp16
    k_scale_x_T<<<dim3(NN / 32, INF_ / 32), dim3(32, 8)>>>(x);
    // 3) weights -> fp16
    k_convert_w<<<128, 256>>>(W1, W2);
    // 4) t1 partials = adjh @ x̃ (grid.y: bit0=N-tile, bits1-2=K-quarter; 512 CTAs)
    k_gemm<NN, NN, NN / 4, 0><<<dim3(NN / 128, 8), 128, SMEM>>>(nullptr, nullptr);
    // 5) t1h = fp16(d * Σ 4 partials)
    k_combine_t1<<<NN * INF_ / 1024, 256>>>();
    // 6) h = relu(t1 @ W1ᵀ + b1)  fp16 [8192,256]  (grid.y = 4 N-tiles)
    k_gemm<INF_, INF_, INF_, 1><<<dim3(NN / 128, HIDF / 64), 128, SMEM>>>(nullptr, b1);
    // 7) p̃ = d ⊙ (h @ W2ᵀ) * 2^14  fp16 [8192,64]
    k_gemm<HIDF, HIDF, HIDF, 2><<<dim3(NN / 128, 1), 128, SMEM>>>(nullptr, nullptr);
    // 8) p̃ᵀ [64][8192]
    k_transpose_p<<<dim3(NN / 32, OUTF / 32), dim3(32, 8)>>>();
    // 9) out partials = adjh @ p̃ᵀ (split-K 8-way, 512 CTAs, adj read once)
    k_gemm<NN, NN, NN / 8, 3><<<dim3(NN / 128, 8), 128, SMEM>>>(nullptr, nullptr);
    // 10) out = Σ 8 partials ⊙ d / 2^14 + b2
    k_combine<<<NN * OUTF / 1024, 256>>>(out, b2);
}

// round 16
// speedup vs baseline: 1.0761x; 1.0761x over previous
#include <cuda_runtime.h>
#include <cuda_fp16.h>
#include <cstdint>

#define NN   8192
#define INF_ 128
#define HIDF 256
#define OUTF 64

// ---------------- scratch (device globals; no allocations allowed) ----------
// NOTE: only ever referenced from device code (host shadow-address bug, R2/R3).
static __device__ __half g_adjh[(size_t)NN * NN];     // adj in fp16 (128 MB)
static __device__ float  g_d[NN];                     // 1/sqrt(deg+eps)
static __device__ __half g_xsT[(size_t)INF_ * NN];    // (d*x)^T  [128][8192]
static __device__ __half g_t1h[(size_t)NN * INF_];    // d⊙(adj@x̃) fp16
static __device__ float  g_t1p[2][(size_t)NN * INF_]; // GEMM1 split-K partials
static __device__ __half g_w1h[(size_t)HIDF * INF_];  // W1 fp16 [256][128]
static __device__ __half g_w2h[(size_t)OUTF * HIDF];  // W2 fp16 [64][256]
static __device__ __half g_h  [(size_t)NN * HIDF];    // relu(t1@W1T+b1) fp16
static __device__ __half g_p  [(size_t)NN * OUTF];    // d*2^14*(h@W2T) fp16
static __device__ __half g_pT [(size_t)OUTF * NN];    // transposed [64][8192]
static __device__ float  g_part[4][(size_t)NN * OUTF]; // GEMM2 split-K partials

// ---------------- helpers ---------------------------------------------------
__device__ __forceinline__ uint32_t smem_u32(const void* p) {
    uint32_t a;
    asm("{ .reg .u64 t; cvta.to.shared.u64 t, %1; cvt.u32.u64 %0, t; }"
        : "=r"(a) : "l"(p));
    return a;
}
__device__ __forceinline__ void cp_async16s(uint32_t s, const void* g) {
    asm volatile("cp.async.cg.shared.global [%0], [%1], 16;\n" :: "r"(s), "l"(g));
}
#define CP_COMMIT() asm volatile("cp.async.commit_group;\n")
#define CP_WAIT(n)  asm volatile("cp.async.wait_group %0;\n" :: "n"(n))

__device__ __forceinline__ void mma16816(float* c, const uint32_t* a, const uint32_t* b) {
    asm volatile(
        "mma.sync.aligned.m16n8k16.row.col.f32.f16.f16.f32 "
        "{%0,%1,%2,%3}, {%4,%5,%6,%7}, {%8,%9}, {%0,%1,%2,%3};\n"
        : "+f"(c[0]), "+f"(c[1]), "+f"(c[2]), "+f"(c[3])
        : "r"(a[0]), "r"(a[1]), "r"(a[2]), "r"(a[3]), "r"(b[0]), "r"(b[1]));
}
__device__ __forceinline__ void ldsm_x4(uint32_t* r, uint32_t addr) {
    asm volatile("ldmatrix.sync.aligned.m8n8.x4.shared.b16 {%0,%1,%2,%3}, [%4];"
        : "=r"(r[0]), "=r"(r[1]), "=r"(r[2]), "=r"(r[3]) : "r"(addr));
}

// ---------------- kernel 1: row-sum + fp32->fp16 convert, one pass ----------
__global__ void __launch_bounds__(256) k_deg_convert(const float* __restrict__ adj) {
    int row = blockIdx.x;
    const float4* src = reinterpret_cast<const float4*>(adj + (size_t)row * NN);
    uint2* dst = reinterpret_cast<uint2*>(g_adjh + (size_t)row * NN);
    float s = 0.f;
    for (int i = threadIdx.x; i < NN / 4; i += 256) {
        float4 v = src[i];
        s += (v.x + v.y) + (v.z + v.w);
        __half2 h0 = __floats2half2_rn(v.x, v.y);
        __half2 h1 = __floats2half2_rn(v.z, v.w);
        uint2 u;
        u.x = *reinterpret_cast<uint32_t*>(&h0);
        u.y = *reinterpret_cast<uint32_t*>(&h1);
        dst[i] = u;
    }
    __shared__ float red[8];
    for (int o = 16; o; o >>= 1) s += __shfl_xor_sync(0xffffffffu, s, o);
    if ((threadIdx.x & 31) == 0) red[threadIdx.x >> 5] = s;
    __syncthreads();
    if (threadIdx.x < 8) {
        float v = red[threadIdx.x];
        for (int o = 4; o; o >>= 1) v += __shfl_xor_sync(0xffu, v, o);
        if (threadIdx.x == 0) g_d[row] = rsqrtf(v + 1e-8f);
    }
}

// ---------------- kernel 2: x̃ᵀ[j][k] = fp16(d_k * x[k][j]) ------------------
__global__ void k_scale_x_T(const float* __restrict__ x) {
    __shared__ float tile[32][33];
    int k0 = blockIdx.x * 32, j0 = blockIdx.y * 32;
    int tx = threadIdx.x, ty = threadIdx.y;   // 32 x 8
    #pragma unroll
    for (int i = 0; i < 32; i += 8) {
        int k = k0 + ty + i;
        tile[ty + i][tx] = x[(size_t)k * INF_ + j0 + tx] * g_d[k];
    }
    __syncthreads();
    #pragma unroll
    for (int i = 0; i < 32; i += 8)
        g_xsT[(size_t)(j0 + ty + i) * NN + k0 + tx] = __float2half(tile[tx][ty + i]);
}

// ---------------- weights -> fp16 -------------------------------------------
__global__ void __launch_bounds__(256) k_convert_w(const float* __restrict__ W1,
                                                   const float* __restrict__ W2) {
    int i = blockIdx.x * 256 + threadIdx.x;
    if (i < HIDF * INF_) g_w1h[i] = __float2half(W1[i]);
    if (i < OUTF * HIDF) g_w2h[i] = __float2half(W2[i]);
}

// ---------------- unified HMMA GEMM ------------------------------------------
// CTA tile 128x64, 128 threads = 4 warps (wm2 x wn2), warp tile 64x32.
// BK=64, S=4 cp.async stages (3-stage prefetch distance covers DRAM latency
// jitter; 110.6 KB/CTA -> 2 CTAs/SM = 221 KB), ldmatrix feed, frag pipeline
// across 4 ks-steps. Pitch 72. R13 loop structure (collective wait+barrier
// at head — the only ordering that makes cross-thread cp.async reads safe).
// KK = K elements per CTA.
// MODE 0 (t1):   A=adjh, B=xsT. grid.y(4): bit0=N-tile, bit1=K-half.
//                raw fp32 -> g_t1p[y>>1].
// MODE 1 (mlp1): A=g_t1h(128), B=g_w1h(128), grid.y = N-tile(4), epi relu+b.
// MODE 2 (mlp2): A=g_h(256),   B=g_w2h(256), grid.y=1, epi d*2^14 -> g_p.
// MODE 3 (out):  A=adjh, B=pT. grid.y = K-quarter(4), raw fp32 -> g_part[y].
template<int LDA, int LDB, int KK, int MODE>
__global__ void __launch_bounds__(128, 2) k_gemm(float* __restrict__ C_arg,
                                                 const float* __restrict__ bias) {
    constexpr int S = 4;
    constexpr int BK = 64;                         // halves of K per stage
    constexpr int KT = KK / BK;
    constexpr int PITCH = BK + 8;                  // 72 halves per row
    constexpr int AH = 128 * PITCH;                // halves per A stage
    constexpr int BH = 64 * PITCH;                 // halves per B stage
    constexpr bool SPLITK = (MODE == 0 || MODE == 3);
    extern __shared__ __half smem_dyn[];
    __half* sAp = smem_dyn;                        // S * AH
    __half* sBp = smem_dyn + S * AH;               // S * BH

    // in-kernel symbol selection (host-shadow rule)
    const __half* A  = SPLITK ? g_adjh : (MODE == 1 ? g_t1h : g_h);
    const __half* BT = (MODE == 0) ? g_xsT
                     : (MODE == 1) ? g_w1h
                     : (MODE == 2) ? g_w2h : g_pT;

    int tid = threadIdx.x;
    int m0 = blockIdx.x * 128;
    int n0, koff;
    if constexpr (MODE == 0) { n0 = (blockIdx.y & 1) * 64; koff = (blockIdx.y >> 1) * KK; }
    else if constexpr (MODE == 3) { n0 = 0; koff = blockIdx.y * KK; }
    else { n0 = blockIdx.y * 64; koff = 0; }
    const __half* gA = A + (size_t)m0 * LDA + koff;
    const __half* gB = BT + (size_t)n0 * LDB + koff;

    const uint32_t uA = smem_u32(sAp);
    const uint32_t uB = smem_u32(sBp);

    auto load_stage = [&](int st, int kt) {
        const __half* a = gA + kt * BK;
        #pragma unroll
        for (int i = 0; i < 8; i++) {              // A: 128 rows x 8 chunks
            int c = tid + i * 128;
            int r = c >> 3, off = (c & 7) << 3;
            cp_async16s(uA + (uint32_t)((st * 128 + r) * PITCH + off) * 2,
                        a + (size_t)r * LDA + off);
        }
        const __half* b = gB + kt * BK;
        #pragma unroll
        for (int i = 0; i < 4; i++) {              // B: 64 rows x 8 chunks
            int c = tid + i * 128;
            int r = c >> 3, off = (c & 7) << 3;
            cp_async16s(uB + (uint32_t)((st * 64 + r) * PITCH + off) * 2,
                        b + (size_t)r * LDB + off);
        }
    };

    #pragma unroll
    for (int s = 0; s < S - 1; s++) {
        if (s < KT) load_stage(s, s);              // guard for short-K modes
        CP_COMMIT();
    }

    int lane = tid & 31, warp = tid >> 5;          // 4 warps
    int wm = warp >> 1, wn = warp & 1;
    int g = lane >> 2, tg = lane & 3;

    // ldmatrix lane roles
    int a_row = (lane & 15);                       // + wm*64 + mt*16
    int a_kof = (lane >> 4) << 3;                  // halves within k16 group
    int b_row = (lane >> 4) * 8 + (lane & 7);      // + wn*32 + j*16
    int b_kof = ((lane >> 3) & 1) << 3;            // halves within k16 group

    float acc[4][4][4];
    #pragma unroll
    for (int mt = 0; mt < 4; mt++)
        #pragma unroll
        for (int nt = 0; nt < 4; nt++)
            #pragma unroll
            for (int i = 0; i < 4; i++) acc[mt][nt][i] = 0.f;

    uint32_t af[2][4][4], bf[2][4][2];
    auto ldfrags = [&](int fb, uint32_t bufA, uint32_t bufB, int ks) {
        #pragma unroll
        for (int mt = 0; mt < 4; mt++) {
            uint32_t addr = bufA
                + (uint32_t)((wm * 64 + mt * 16 + a_row) * PITCH
                             + ks * 16 + a_kof) * 2;
            ldsm_x4(af[fb][mt], addr);
        }
        #pragma unroll
        for (int j = 0; j < 2; j++) {
            uint32_t r4[4];
            uint32_t addr = bufB
                + (uint32_t)((wn * 32 + j * 16 + b_row) * PITCH
                             + ks * 16 + b_kof) * 2;
            ldsm_x4(r4, addr);
            bf[fb][2 * j][0] = r4[0]; bf[fb][2 * j][1] = r4[1];
            bf[fb][2 * j + 1][0] = r4[2]; bf[fb][2 * j + 1][1] = r4[3];
        }
    };

    for (int kt = 0; kt < KT; kt++) {
        CP_WAIT(S - 2);
        __syncthreads();
        int buf = kt % S;
        uint32_t bufA = uA + (uint32_t)(buf * AH) * 2;
        uint32_t bufB = uB + (uint32_t)(buf * BH) * 2;
        ldfrags(0, bufA, bufB, 0);                 // head frags (latency hidden
                                                   // behind load_stage issue)
        int nk = kt + S - 1;
        if (nk < KT) load_stage(nk % S, nk);       // async: next stage
        CP_COMMIT();
        #pragma unroll
        for (int ks = 0; ks < 4; ks++) {           // 4 k16 steps per stage
            int fb = ks & 1;
            if (ks < 3) ldfrags(fb ^ 1, bufA, bufB, ks + 1);
            #pragma unroll
            for (int mt = 0; mt < 4; mt++)
                #pragma unroll
                for (int nt = 0; nt < 4; nt++)
                    mma16816(acc[mt][nt], af[fb][mt], bf[fb][nt]);
        }
    }

    // ------ epilogue ------
    float* part = (MODE == 0) ? g_t1p[blockIdx.y >> 1]
                : (MODE == 3) ? g_part[blockIdx.y] : nullptr;
    constexpr int LDC = (MODE == 0) ? INF_ : OUTF;
    #pragma unroll
    for (int mt = 0; mt < 4; mt++) {
        int r0 = m0 + wm * 64 + mt * 16 + g;
        int r1 = r0 + 8;
        #pragma unroll
        for (int nt = 0; nt < 4; nt++) {
            int c = n0 + wn * 32 + nt * 8 + 2 * tg;
            float v00 = acc[mt][nt][0], v01 = acc[mt][nt][1];
            float v10 = acc[mt][nt][2], v11 = acc[mt][nt][3];
            if constexpr (SPLITK) {                // raw partials, combined later
                *(float2*)(part + (size_t)r0 * LDC + c) = make_float2(v00, v01);
                *(float2*)(part + (size_t)r1 * LDC + c) = make_float2(v10, v11);
            } else if constexpr (MODE == 1) {
                float b0 = bias[c], b1v = bias[c + 1];
                *(__half2*)(g_h + (size_t)r0 * HIDF + c) =
                    __floats2half2_rn(fmaxf(v00 + b0, 0.f), fmaxf(v01 + b1v, 0.f));
                *(__half2*)(g_h + (size_t)r1 * HIDF + c) =
                    __floats2half2_rn(fmaxf(v10 + b0, 0.f), fmaxf(v11 + b1v, 0.f));
            } else {                               // MODE 2
                float d0 = g_d[r0] * 16384.f, d1 = g_d[r1] * 16384.f;
                *(__half2*)(g_p + (size_t)r0 * OUTF + c) =
                    __floats2half2_rn(v00 * d0, v01 * d0);
                *(__half2*)(g_p + (size_t)r1 * OUTF + c) =
                    __floats2half2_rn(v10 * d1, v11 * d1);
            }
        }
    }
}

// ---------------- combine GEMM1 split-K: t1h = fp16(d * (p0 + p1)) ----------
__global__ void __launch_bounds__(256) k_combine_t1() {
    int idx = blockIdx.x * 256 + threadIdx.x;      // one float4-pair per thread
    int r = (idx * 4) / INF_;
    float4 a = *reinterpret_cast<const float4*>(&g_t1p[0][(size_t)idx * 4]);
    float4 b = *reinterpret_cast<const float4*>(&g_t1p[1][(size_t)idx * 4]);
    float dsc = g_d[r];
    __half2 h0 = __floats2half2_rn((a.x + b.x) * dsc, (a.y + b.y) * dsc);
    __half2 h1 = __floats2half2_rn((a.z + b.z) * dsc, (a.w + b.w) * dsc);
    uint2 u;
    u.x = *reinterpret_cast<uint32_t*>(&h0);
    u.y = *reinterpret_cast<uint32_t*>(&h1);
    *reinterpret_cast<uint2*>(g_t1h + (size_t)idx * 4) = u;
}

// ---------------- combine GEMM2 split-K: out = (Σp)*d/2^14 + b2 -------------
__global__ void __launch_bounds__(256) k_combine(float* __restrict__ out,
                                                 const float* __restrict__ b2) {
    int idx = blockIdx.x * 256 + threadIdx.x;      // one float4 per thread
    int r = (idx * 4) / OUTF, c = (idx * 4) % OUTF;
    float4 a = *reinterpret_cast<const float4*>(&g_part[0][(size_t)idx * 4]);
    float4 b = *reinterpret_cast<const float4*>(&g_part[1][(size_t)idx * 4]);
    float4 e = *reinterpret_cast<const float4*>(&g_part[2][(size_t)idx * 4]);
    float4 f = *reinterpret_cast<const float4*>(&g_part[3][(size_t)idx * 4]);
    float dsc = g_d[r] * (1.f / 16384.f);
    float4 o;
    o.x = ((a.x + b.x) + (e.x + f.x)) * dsc + b2[c];
    o.y = ((a.y + b.y) + (e.y + f.y)) * dsc + b2[c + 1];
    o.z = ((a.z + b.z) + (e.z + f.z)) * dsc + b2[c + 2];
    o.w = ((a.w + b.w) + (e.w + f.w)) * dsc + b2[c + 3];
    *reinterpret_cast<float4*>(out + (size_t)idx * 4) = o;
}

// ---------------- transpose g_p [8192,64] -> g_pT [64][8192] ----------------
__global__ void k_transpose_p() {
    __shared__ __half tile[32][33];
    int k0 = blockIdx.x * 32, c0 = blockIdx.y * 32;
    int tx = threadIdx.x, ty = threadIdx.y;   // 32 x 8
    #pragma unroll
    for (int i = 0; i < 32; i += 8)
        tile[ty + i][tx] = g_p[(size_t)(k0 + ty + i) * OUTF + c0 + tx];
    __syncthreads();
    #pragma unroll
    for (int i = 0; i < 32; i += 8)
        g_pT[(size_t)(c0 + ty + i) * NN + k0 + tx] = tile[tx][ty + i];
}

// ---------------- launch -----------------------------------------------------
extern "C" void kernel_launch(void* const* d_in, const int* in_sizes, int n_in,
                              void* d_out, int out_size) {
    const float* x   = (const float*)d_in[0];
    const float* adj = (const float*)d_in[1];
    const float* W1  = (const float*)d_in[2];
    const float* b1  = (const float*)d_in[3];
    const float* W2  = (const float*)d_in[4];
    const float* b2  = (const float*)d_in[5];
    float* out = (float*)d_out;

    // dynamic smem: S=4, 4*(128+64)*72 halves * 2B = 110592 (2 CTAs/SM: 221KB)
    constexpr int SMEM = 4 * (128 + 64) * 72 * 2;
    cudaFuncSetAttribute(k_gemm<NN, NN, NN / 2, 0>,
                         cudaFuncAttributeMaxDynamicSharedMemorySize, SMEM);
    cudaFuncSetAttribute(k_gemm<INF_, INF_, INF_, 1>,
                         cudaFuncAttributeMaxDynamicSharedMemorySize, SMEM);
    cudaFuncSetAttribute(k_gemm<HIDF, HIDF, HIDF, 2>,
                         cudaFuncAttributeMaxDynamicSharedMemorySize, SMEM);
    cudaFuncSetAttribute(k_gemm<NN, NN, NN / 4, 3>,
                         cudaFuncAttributeMaxDynamicSharedMemorySize, SMEM);

    // 1) degrees + adj->fp16 (one pass over 256 MB)
    k_deg_convert<<<NN, 256>>>(adj);
    // 2) x̃ᵀ = (d ⊙ x)ᵀ fp16
    k_scale_x_T<<<dim3(NN / 32, INF_ / 32), dim3(32, 8)>>>(x);
    // 3) weights -> fp16
    k_convert_w<<<128, 256>>>(W1, W2);
    // 4) t1 partials = adjh @ x̃ (grid.y: bit0=N-tile, bit1=K-half; 256 CTAs)
    k_gemm<NN, NN, NN / 2, 0><<<dim3(NN / 128, 4), 128, SMEM>>>(nullptr, nullptr);
    // 5) t1h = fp16(d * (p0+p1))
    k_combine_t1<<<NN * INF_ / 1024, 256>>>();
    // 6) h = relu(t1 @ W1ᵀ + b1)  fp16 [8192,256]  (grid.y = 4 N-tiles)
    k_gemm<INF_, INF_, INF_, 1><<<dim3(NN / 128, HIDF / 64), 128, SMEM>>>(nullptr, b1);
    // 7) p̃ = d ⊙ (h @ W2ᵀ) * 2^14  fp16 [8192,64]
    k_gemm<HIDF, HIDF, HIDF, 2><<<dim3(NN / 128, 1), 128, SMEM>>>(nullptr, nullptr);
    // 8) p̃ᵀ [64][8192]
    k_transpose_p<<<dim3(NN / 32, OUTF / 32), dim3(32, 8)>>>();
    // 9) out partials = adjh @ p̃ᵀ (split-K 4-way, 256 CTAs, adj read once)
    k_gemm<NN, NN, NN / 4, 3><<<dim3(NN / 128, 4), 128, SMEM>>>(nullptr, nullptr);
    // 10) out = Σ 4 partials ⊙ d / 2^14 + b2
    k_combine<<<NN * OUTF / 1024, 256>>>(out, b2);
}

// round 17
// speedup vs baseline: 1.1465x; 1.0654x over previous
#include <cuda_runtime.h>
#include <cuda_fp16.h>
#include <cstdint>

#define NN   8192
#define INF_ 128
#define HIDF 256
#define OUTF 64

// ---------------- scratch (device globals; no allocations allowed) ----------
// NOTE: only ever referenced from device code (host shadow-address bug, R2/R3).
static __device__ __half g_adjh[(size_t)NN * NN];     // adj in fp16 (128 MB)
static __device__ float  g_d[NN];                     // 1/sqrt(deg+eps)
static __device__ __half g_xsT[(size_t)INF_ * NN];    // (d*x)^T  [128][8192]
static __device__ __half g_t1h[(size_t)NN * INF_];    // d⊙(adj@x̃) fp16
static __device__ float  g_t1p[4][(size_t)NN * INF_]; // GEMM1 split-K partials
static __device__ __half g_w1h[(size_t)HIDF * INF_];  // W1 fp16 [256][128]
static __device__ __half g_w2h[(size_t)OUTF * HIDF];  // W2 fp16 [64][256]
static __device__ __half g_h  [(size_t)NN * HIDF];    // relu(t1@W1T+b1) fp16
static __device__ __half g_p  [(size_t)NN * OUTF];    // d*2^14*(h@W2T) fp16
static __device__ __half g_pT [(size_t)OUTF * NN];    // transposed [64][8192]
static __device__ float  g_part[4][(size_t)NN * OUTF]; // GEMM2 split-K partials

// ---------------- helpers ---------------------------------------------------
__device__ __forceinline__ uint32_t smem_u32(const void* p) {
    uint32_t a;
    asm("{ .reg .u64 t; cvta.to.shared.u64 t, %1; cvt.u32.u64 %0, t; }"
        : "=r"(a) : "l"(p));
    return a;
}
__device__ __forceinline__ void cp_async16s(uint32_t s, const void* g) {
    asm volatile("cp.async.cg.shared.global [%0], [%1], 16;\n" :: "r"(s), "l"(g));
}
#define CP_COMMIT() asm volatile("cp.async.commit_group;\n")
#define CP_WAIT(n)  asm volatile("cp.async.wait_group %0;\n" :: "n"(n))

__device__ __forceinline__ void mma16816(float* c, const uint32_t* a, const uint32_t* b) {
    asm volatile(
        "mma.sync.aligned.m16n8k16.row.col.f32.f16.f16.f32 "
        "{%0,%1,%2,%3}, {%4,%5,%6,%7}, {%8,%9}, {%0,%1,%2,%3};\n"
        : "+f"(c[0]), "+f"(c[1]), "+f"(c[2]), "+f"(c[3])
        : "r"(a[0]), "r"(a[1]), "r"(a[2]), "r"(a[3]), "r"(b[0]), "r"(b[1]));
}
__device__ __forceinline__ void ldsm_x4(uint32_t* r, uint32_t addr) {
    asm volatile("ldmatrix.sync.aligned.m8n8.x4.shared.b16 {%0,%1,%2,%3}, [%4];"
        : "=r"(r[0]), "=r"(r[1]), "=r"(r[2]), "=r"(r[3]) : "r"(addr));
}

// ---------------- kernel 1: row-sum + fp32->fp16 convert, one pass ----------
__global__ void __launch_bounds__(256) k_deg_convert(const float* __restrict__ adj) {
    int row = blockIdx.x;
    const float4* src = reinterpret_cast<const float4*>(adj + (size_t)row * NN);
    uint2* dst = reinterpret_cast<uint2*>(g_adjh + (size_t)row * NN);
    float s = 0.f;
    for (int i = threadIdx.x; i < NN / 4; i += 256) {
        float4 v = src[i];
        s += (v.x + v.y) + (v.z + v.w);
        __half2 h0 = __floats2half2_rn(v.x, v.y);
        __half2 h1 = __floats2half2_rn(v.z, v.w);
        uint2 u;
        u.x = *reinterpret_cast<uint32_t*>(&h0);
        u.y = *reinterpret_cast<uint32_t*>(&h1);
        dst[i] = u;
    }
    __shared__ float red[8];
    for (int o = 16; o; o >>= 1) s += __shfl_xor_sync(0xffffffffu, s, o);
    if ((threadIdx.x & 31) == 0) red[threadIdx.x >> 5] = s;
    __syncthreads();
    if (threadIdx.x < 8) {
        float v = red[threadIdx.x];
        for (int o = 4; o; o >>= 1) v += __shfl_xor_sync(0xffu, v, o);
        if (threadIdx.x == 0) g_d[row] = rsqrtf(v + 1e-8f);
    }
}

// ---------------- kernel 2: x̃ᵀ[j][k] = fp16(d_k * x[k][j]) ------------------
__global__ void k_scale_x_T(const float* __restrict__ x) {
    __shared__ float tile[32][33];
    int k0 = blockIdx.x * 32, j0 = blockIdx.y * 32;
    int tx = threadIdx.x, ty = threadIdx.y;   // 32 x 8
    #pragma unroll
    for (int i = 0; i < 32; i += 8) {
        int k = k0 + ty + i;
        tile[ty + i][tx] = x[(size_t)k * INF_ + j0 + tx] * g_d[k];
    }
    __syncthreads();
    #pragma unroll
    for (int i = 0; i < 32; i += 8)
        g_xsT[(size_t)(j0 + ty + i) * NN + k0 + tx] = __float2half(tile[tx][ty + i]);
}

// ---------------- weights -> fp16 -------------------------------------------
__global__ void __launch_bounds__(256) k_convert_w(const float* __restrict__ W1,
                                                   const float* __restrict__ W2) {
    int i = blockIdx.x * 256 + threadIdx.x;
    if (i < HIDF * INF_) g_w1h[i] = __float2half(W1[i]);
    if (i < OUTF * HIDF) g_w2h[i] = __float2half(W2[i]);
}

// ---------------- unified HMMA GEMM ------------------------------------------
// CTA tile 128xBN, 128 threads = 4 warps (wm2 x wn2), warp tile 64x(BN/2).
// BN=128: NT=8, FLOP/smem-byte 32, 128 MMAs/warp/kt, S=3 (110.6 KB, 2 CTAs/SM).
// BN=64:  NT=4 (proven R16 config), S=4 (also 110.6 KB, 2 CTAs/SM).
// BK=64, pitch 72, ldmatrix feed, frag double-buffer across 4 ks-steps.
// KK = K elements per CTA.
// MODE 0 (t1):   A=adjh, B=xsT, BN=128. grid.y = K-quarter(4),
//                raw fp32 -> g_t1p[y].
// MODE 1 (mlp1): A=g_t1h(128), B=g_w1h(128), BN=128, grid.y = N-tile(2),
//                epi relu+b.
// MODE 2 (mlp2): A=g_h(256),   B=g_w2h(256), BN=64, grid.y=1, epi d*2^14.
// MODE 3 (out):  A=adjh, B=pT, BN=64. grid.y = K-quarter(4),
//                raw fp32 -> g_part[y].
template<int LDA, int LDB, int KK, int MODE, int BN>
__global__ void __launch_bounds__(128, 2) k_gemm(float* __restrict__ C_arg,
                                                 const float* __restrict__ bias) {
    constexpr int S = (BN == 128) ? 3 : 4;
    constexpr int BK = 64;                         // halves of K per stage
    constexpr int KT = KK / BK;
    constexpr int PITCH = BK + 8;                  // 72 halves per row
    constexpr int AH = 128 * PITCH;                // halves per A stage
    constexpr int BH = BN * PITCH;                 // halves per B stage
    constexpr int WN = BN / 2;                     // warp N extent
    constexpr int NT = WN / 8;                     // n-tiles per warp
    constexpr bool SPLITK = (MODE == 0 || MODE == 3);
    extern __shared__ __half smem_dyn[];
    __half* sAp = smem_dyn;                        // S * AH
    __half* sBp = smem_dyn + S * AH;               // S * BH

    // in-kernel symbol selection (host-shadow rule)
    const __half* A  = SPLITK ? g_adjh : (MODE == 1 ? g_t1h : g_h);
    const __half* BT = (MODE == 0) ? g_xsT
                     : (MODE == 1) ? g_w1h
                     : (MODE == 2) ? g_w2h : g_pT;

    int tid = threadIdx.x;
    int m0 = blockIdx.x * 128;
    int n0, koff;
    if constexpr (SPLITK) { n0 = 0; koff = blockIdx.y * KK; }
    else { n0 = blockIdx.y * BN; koff = 0; }
    const __half* gA = A + (size_t)m0 * LDA + koff;
    const __half* gB = BT + (size_t)n0 * LDB + koff;

    const uint32_t uA = smem_u32(sAp);
    const uint32_t uB = smem_u32(sBp);

    auto load_stage = [&](int st, int kt) {
        const __half* a = gA + kt * BK;
        #pragma unroll
        for (int i = 0; i < 8; i++) {              // A: 128 rows x 8 chunks
            int c = tid + i * 128;
            int r = c >> 3, off = (c & 7) << 3;
            cp_async16s(uA + (uint32_t)((st * 128 + r) * PITCH + off) * 2,
                        a + (size_t)r * LDA + off);
        }
        const __half* b = gB + kt * BK;
        #pragma unroll
        for (int i = 0; i < BN / 16; i++) {        // B: BN rows x 8 chunks
            int c = tid + i * 128;
            int r = c >> 3, off = (c & 7) << 3;
            cp_async16s(uB + (uint32_t)((st * BN + r) * PITCH + off) * 2,
                        b + (size_t)r * LDB + off);
        }
    };

    #pragma unroll
    for (int s = 0; s < S - 1; s++) {
        if (s < KT) load_stage(s, s);              // guard for short-K modes
        CP_COMMIT();
    }

    int lane = tid & 31, warp = tid >> 5;          // 4 warps
    int wm = warp >> 1, wn = warp & 1;
    int g = lane >> 2, tg = lane & 3;

    // ldmatrix lane roles
    int a_row = (lane & 15);                       // + wm*64 + mt*16
    int a_kof = (lane >> 4) << 3;                  // halves within k16 group
    int b_row = (lane >> 4) * 8 + (lane & 7);      // + wn*WN + j*16
    int b_kof = ((lane >> 3) & 1) << 3;            // halves within k16 group

    float acc[4][NT][4];
    #pragma unroll
    for (int mt = 0; mt < 4; mt++)
        #pragma unroll
        for (int nt = 0; nt < NT; nt++)
            #pragma unroll
            for (int i = 0; i < 4; i++) acc[mt][nt][i] = 0.f;

    uint32_t af[2][4][4], bf[2][NT][2];
    auto ldfrags = [&](int fb, uint32_t bufA, uint32_t bufB, int ks) {
        #pragma unroll
        for (int mt = 0; mt < 4; mt++) {
            uint32_t addr = bufA
                + (uint32_t)((wm * 64 + mt * 16 + a_row) * PITCH
                             + ks * 16 + a_kof) * 2;
            ldsm_x4(af[fb][mt], addr);
        }
        #pragma unroll
        for (int j = 0; j < NT / 2; j++) {
            uint32_t r4[4];
            uint32_t addr = bufB
                + (uint32_t)((wn * WN + j * 16 + b_row) * PITCH
                             + ks * 16 + b_kof) * 2;
            ldsm_x4(r4, addr);
            bf[fb][2 * j][0] = r4[0]; bf[fb][2 * j][1] = r4[1];
            bf[fb][2 * j + 1][0] = r4[2]; bf[fb][2 * j + 1][1] = r4[3];
        }
    };

    for (int kt = 0; kt < KT; kt++) {
        CP_WAIT(S - 2);
        __syncthreads();
        int buf = kt % S;
        uint32_t bufA = uA + (uint32_t)(buf * AH) * 2;
        uint32_t bufB = uB + (uint32_t)(buf * BH) * 2;
        ldfrags(0, bufA, bufB, 0);                 // head frags (latency hidden
                                                   // behind load_stage issue)
        int nk = kt + S - 1;
        if (nk < KT) load_stage(nk % S, nk);       // async: next stage
        CP_COMMIT();
        #pragma unroll
        for (int ks = 0; ks < 4; ks++) {           // 4 k16 steps per stage
            int fb = ks & 1;
            if (ks < 3) ldfrags(fb ^ 1, bufA, bufB, ks + 1);
            #pragma unroll
            for (int mt = 0; mt < 4; mt++)
                #pragma unroll
                for (int nt = 0; nt < NT; nt++)
                    mma16816(acc[mt][nt], af[fb][mt], bf[fb][nt]);
        }
    }

    // ------ epilogue ------
    float* part = (MODE == 0) ? g_t1p[blockIdx.y]
                : (MODE == 3) ? g_part[blockIdx.y] : nullptr;
    constexpr int LDC = (MODE == 0) ? INF_ : OUTF;
    #pragma unroll
    for (int mt = 0; mt < 4; mt++) {
        int r0 = m0 + wm * 64 + mt * 16 + g;
        int r1 = r0 + 8;
        #pragma unroll
        for (int nt = 0; nt < NT; nt++) {
            int c = n0 + wn * WN + nt * 8 + 2 * tg;
            float v00 = acc[mt][nt][0], v01 = acc[mt][nt][1];
            float v10 = acc[mt][nt][2], v11 = acc[mt][nt][3];
            if constexpr (SPLITK) {                // raw partials, combined later
                *(float2*)(part + (size_t)r0 * LDC + c) = make_float2(v00, v01);
                *(float2*)(part + (size_t)r1 * LDC + c) = make_float2(v10, v11);
            } else if constexpr (MODE == 1) {
                float b0 = bias[c], b1v = bias[c + 1];
                *(__half2*)(g_h + (size_t)r0 * HIDF + c) =
                    __floats2half2_rn(fmaxf(v00 + b0, 0.f), fmaxf(v01 + b1v, 0.f));
                *(__half2*)(g_h + (size_t)r1 * HIDF + c) =
                    __floats2half2_rn(fmaxf(v10 + b0, 0.f), fmaxf(v11 + b1v, 0.f));
            } else {                               // MODE 2
                float d0 = g_d[r0] * 16384.f, d1 = g_d[r1] * 16384.f;
                *(__half2*)(g_p + (size_t)r0 * OUTF + c) =
                    __floats2half2_rn(v00 * d0, v01 * d0);
                *(__half2*)(g_p + (size_t)r1 * OUTF + c) =
                    __floats2half2_rn(v10 * d1, v11 * d1);
            }
        }
    }
}

// ---------------- combine GEMM1 split-K: t1h = fp16(d * Σ 4 partials) -------
__global__ void __launch_bounds__(256) k_combine_t1() {
    int idx = blockIdx.x * 256 + threadIdx.x;      // one float4 per thread
    int r = (idx * 4) / INF_;
    float4 a = *reinterpret_cast<const float4*>(&g_t1p[0][(size_t)idx * 4]);
    float4 b = *reinterpret_cast<const float4*>(&g_t1p[1][(size_t)idx * 4]);
    float4 e = *reinterpret_cast<const float4*>(&g_t1p[2][(size_t)idx * 4]);
    float4 f = *reinterpret_cast<const float4*>(&g_t1p[3][(size_t)idx * 4]);
    float dsc = g_d[r];
    float sx = (a.x + b.x) + (e.x + f.x);
    float sy = (a.y + b.y) + (e.y + f.y);
    float sz = (a.z + b.z) + (e.z + f.z);
    float sw = (a.w + b.w) + (e.w + f.w);
    __half2 h0 = __floats2half2_rn(sx * dsc, sy * dsc);
    __half2 h1 = __floats2half2_rn(sz * dsc, sw * dsc);
    uint2 u;
    u.x = *reinterpret_cast<uint32_t*>(&h0);
    u.y = *reinterpret_cast<uint32_t*>(&h1);
    *reinterpret_cast<uint2*>(g_t1h + (size_t)idx * 4) = u;
}

// ---------------- combine GEMM2 split-K: out = (Σp)*d/2^14 + b2 -------------
__global__ void __launch_bounds__(256) k_combine(float* __restrict__ out,
                                                 const float* __restrict__ b2) {
    int idx = blockIdx.x * 256 + threadIdx.x;      // one float4 per thread
    int r = (idx * 4) / OUTF, c = (idx * 4) % OUTF;
    float4 a = *reinterpret_cast<const float4*>(&g_part[0][(size_t)idx * 4]);
    float4 b = *reinterpret_cast<const float4*>(&g_part[1][(size_t)idx * 4]);
    float4 e = *reinterpret_cast<const float4*>(&g_part[2][(size_t)idx * 4]);
    float4 f = *reinterpret_cast<const float4*>(&g_part[3][(size_t)idx * 4]);
    float dsc = g_d[r] * (1.f / 16384.f);
    float4 o;
    o.x = ((a.x + b.x) + (e.x + f.x)) * dsc + b2[c];
    o.y = ((a.y + b.y) + (e.y + f.y)) * dsc + b2[c + 1];
    o.z = ((a.z + b.z) + (e.z + f.z)) * dsc + b2[c + 2];
    o.w = ((a.w + b.w) + (e.w + f.w)) * dsc + b2[c + 3];
    *reinterpret_cast<float4*>(out + (size_t)idx * 4) = o;
}

// ---------------- transpose g_p [8192,64] -> g_pT [64][8192] ----------------
__global__ void k_transpose_p() {
    __shared__ __half tile[32][33];
    int k0 = blockIdx.x * 32, c0 = blockIdx.y * 32;
    int tx = threadIdx.x, ty = threadIdx.y;   // 32 x 8
    #pragma unroll
    for (int i = 0; i < 32; i += 8)
        tile[ty + i][tx] = g_p[(size_t)(k0 + ty + i) * OUTF + c0 + tx];
    __syncthreads();
    #pragma unroll
    for (int i = 0; i < 32; i += 8)
        g_pT[(size_t)(c0 + ty + i) * NN + k0 + tx] = tile[tx][ty + i];
}

// ---------------- launch -----------------------------------------------------
extern "C" void kernel_launch(void* const* d_in, const int* in_sizes, int n_in,
                              void* d_out, int out_size) {
    const float* x   = (const float*)d_in[0];
    const float* adj = (const float*)d_in[1];
    const float* W1  = (const float*)d_in[2];
    const float* b1  = (const float*)d_in[3];
    const float* W2  = (const float*)d_in[4];
    const float* b2  = (const float*)d_in[5];
    float* out = (float*)d_out;

    // dynamic smem: BN=128 S=3 and BN=64 S=4 both = 110592 B (2 CTAs/SM: 221KB)
    constexpr int SMEM = 110592;
    cudaFuncSetAttribute(k_gemm<NN, NN, NN / 4, 0, 128>,
                         cudaFuncAttributeMaxDynamicSharedMemorySize, SMEM);
    cudaFuncSetAttribute(k_gemm<INF_, INF_, INF_, 1, 128>,
                         cudaFuncAttributeMaxDynamicSharedMemorySize, SMEM);
    cudaFuncSetAttribute(k_gemm<HIDF, HIDF, HIDF, 2, 64>,
                         cudaFuncAttributeMaxDynamicSharedMemorySize, SMEM);
    cudaFuncSetAttribute(k_gemm<NN, NN, NN / 4, 3, 64>,
                         cudaFuncAttributeMaxDynamicSharedMemorySize, SMEM);

    // 1) degrees + adj->fp16 (one pass over 256 MB)
    k_deg_convert<<<NN, 256>>>(adj);
    // 2) x̃ᵀ = (d ⊙ x)ᵀ fp16
    k_scale_x_T<<<dim3(NN / 32, INF_ / 32), dim3(32, 8)>>>(x);
    // 3) weights -> fp16
    k_convert_w<<<128, 256>>>(W1, W2);
    // 4) t1 partials = adjh @ x̃ (full N=128 tile, K-split 4; 256 CTAs)
    k_gemm<NN, NN, NN / 4, 0, 128><<<dim3(NN / 128, 4), 128, SMEM>>>(nullptr, nullptr);
    // 5) t1h = fp16(d * Σ 4 partials)
    k_combine_t1<<<NN * INF_ / 1024, 256>>>();
    // 6) h = relu(t1 @ W1ᵀ + b1)  fp16 [8192,256]  (grid.y = 2 N-tiles)
    k_gemm<INF_, INF_, INF_, 1, 128><<<dim3(NN / 128, HIDF / 128), 128, SMEM>>>(nullptr, b1);
    // 7) p̃ = d ⊙ (h @ W2ᵀ) * 2^14  fp16 [8192,64]
    k_gemm<HIDF, HIDF, HIDF, 2, 64><<<dim3(NN / 128, 1), 128, SMEM>>>(nullptr, nullptr);
    // 8) p̃ᵀ [64][8192]
    k_transpose_p<<<dim3(NN / 32, OUTF / 32), dim3(32, 8)>>>();
    // 9) out partials = adjh @ p̃ᵀ (split-K 4-way, 256 CTAs, adj read once)
    k_gemm<NN, NN, NN / 4, 3, 64><<<dim3(NN / 128, 4), 128, SMEM>>>(nullptr, nullptr);
    // 10) out = Σ 4 partials ⊙ d / 2^14 + b2
    k_combine<<<NN * OUTF / 1024, 256>>>(out, b2);
}